// round 10
// baseline (speedup 1.0000x reference)
#include <cuda_runtime.h>

#define NQ  10
#define DIM 1024
#define NL  4
#define TPB 64

typedef unsigned long long u64;

// Hardcoded GF(2) swizzle matrices (fixed CNOT rings; rank-5 verified store+gather).
#define A0_0 1u
#define A0_1 2u
#define A0_2 4u
#define A0_3 9u
#define A0_4 0u
#define A1_0 2u
#define A1_1 4u
#define A1_2 8u
#define A1_3 0x11u
#define A1_4 1u
#define PC0  0x200u
#define PC1  0x201u

__device__ u64 g_gmat[NL * NQ][8];       // packed gate coefficients
__device__ unsigned g_T[2][512];         // gather word-table (unchanged from R9)

__device__ __forceinline__ unsigned amul(int p, unsigned v) {
    unsigned r = 0;
    if (p == 0) {
        if (v & 1u)  r ^= A0_0;
        if (v & 2u)  r ^= A0_1;
        if (v & 4u)  r ^= A0_2;
        if (v & 8u)  r ^= A0_3;
        if (v & 16u) r ^= A0_4;
    } else {
        if (v & 1u)  r ^= A1_0;
        if (v & 2u)  r ^= A1_1;
        if (v & 4u)  r ^= A1_2;
        if (v & 8u)  r ^= A1_3;
        if (v & 16u) r ^= A1_4;
    }
    return r;
}

__device__ __forceinline__ u64 pack2(float x, float y) {
    u64 r; asm("mov.b64 %0, {%1,%2};" : "=l"(r) : "f"(x), "f"(y)); return r;
}
__device__ __forceinline__ void unpk(u64 v, float& x, float& y) {
    asm("mov.b64 {%0,%1}, %2;" : "=f"(x), "=f"(y) : "l"(v));
}
__device__ __forceinline__ u64 swp(u64 v) {
    u64 r;
    asm("{\n\t.reg .b32 lo, hi;\n\tmov.b64 {lo,hi}, %1;\n\tmov.b64 %0, {hi,lo};\n\t}"
        : "=l"(r) : "l"(v));
    return r;
}
__device__ __forceinline__ u64 ffma2(u64 a, u64 b, u64 c) {
    u64 d; asm("fma.rn.f32x2 %0, %1, %2, %3;" : "=l"(d) : "l"(a), "l"(b), "l"(c)); return d;
}
__device__ __forceinline__ u64 fmul2(u64 a, u64 b) {
    u64 d; asm("mul.rn.f32x2 %0, %1, %2;" : "=l"(d) : "l"(a), "l"(b)); return d;
}
__device__ __forceinline__ u64 fadd2(u64 a, u64 b) {
    u64 d; asm("add.rn.f32x2 %0, %1, %2;" : "=l"(d) : "l"(a), "l"(b)); return d;
}
__device__ __forceinline__ float2 cmulf(float2 a, float2 b) {
    return make_float2(a.x * b.x - a.y * b.y, a.x * b.y + a.y * b.x);
}

__device__ __forceinline__ unsigned finv10(int type, unsigned idx) {
    int off = type ? (NQ / 2) : 1;
    unsigned y = idx;
    #pragma unroll
    for (int i = NQ - 1; i >= 0; --i) {
        int bc = NQ - 1 - i;
        int bt = NQ - 1 - ((i + off) % NQ);
        y ^= ((y >> bc) & 1u) << bt;
    }
    return y;
}

__global__ void precompute_kernel(const float* __restrict__ w) {
    int t = threadIdx.x;

    if (t < NL * NQ) {
        int l = t / NQ, q = t % NQ;
        float w0 = w[t * 3 + 0], w1 = w[t * 3 + 1], w2 = w[t * 3 + 2];
        float sb, cb; sincosf(0.5f * w1, &sb, &cb);
        u64* g = g_gmat[t];
        if (q >= 1 && q <= 5) {
            // diag form: RY real coeffs + RZ scalars + post-ratio
            float s0, c0; sincosf(0.5f * w0, &s0, &c0);   // pre0  = e^{-i w0/2}
            float s2, c2; sincosf(0.5f * w2, &s2, &c2);   // post0 = e^{-i w2/2}
            float sr, cr; sincosf(w2, &sr, &cr);          // ratio = e^{+i w2}
            g[0] = pack2(cb, cb);
            g[1] = pack2(sb, sb);
            g[2] = pack2(-sb, -sb);
            g[3] = pack2(c0, -s0);
            g[4] = pack2(c2, -s2);
            if (q == 1) {
                // POSTBASE = prod_{q=2..5} e^{-i w2_q/2}
                float S = 0.0f;
                #pragma unroll
                for (int qq = 2; qq <= 5; ++qq) S += w[(l * NQ + qq) * 3 + 2];
                float sS, cS; sincosf(0.5f * S, &sS, &cS);
                g[5] = pack2(cS, -sS);
                g[6] = 0; g[7] = 0;
            } else {
                g[5] = pack2(cr, cr);     // ratio C
                g[6] = pack2(-sr, sr);    // ratio D
                g[7] = 0;
            }
        } else {
            float sp, cp; sincosf(0.5f * (w0 + w2), &sp, &cp);
            float sd, cd; sincosf(0.5f * (w0 - w2), &sd, &cd);
            float ar = cb * cp, ai = -cb * sp;   // U00
            float br = sb * cd, bi = -sb * sd;   // U10 ; U01=-conj(U10), U11=conj(U00)
            if (q == 0) {
                // merged-gather layout: {c00,d00,c01,d01, c11,d11,c10,d10}
                g[0] = pack2(ar, ar);   g[1] = pack2(-ai, ai);
                g[2] = pack2(-br, -br); g[3] = pack2(-bi, bi);
                g[4] = pack2(ar, ar);   g[5] = pack2(ai, -ai);
                g[6] = pack2(br, br);   g[7] = pack2(-bi, bi);
            } else {
                // standard layout: {c00,d00,c01,d01,c10,d10,c11,d11}
                g[0] = pack2(ar, ar);   g[1] = pack2(-ai, ai);
                g[2] = pack2(-br, -br); g[3] = pack2(-bi, bi);
                g[4] = pack2(br, br);   g[5] = pack2(-bi, bi);
                g[6] = pack2(ar, ar);   g[7] = pack2(ai, -ai);
            }
        }
    }

    // gather word-table (identical to R9)
    for (int i = t; i < 2 * 512; i += blockDim.x) {
        int p = i >> 9, widx = i & 511;
        int W = widx >> 8, lane = (widx >> 3) & 31, cs = widx & 7;
        int c = cs ^ (lane >> 2);
        unsigned j0 = (unsigned)(W * 512 + lane * 16 + 2 * c);
        unsigned e[2];
        #pragma unroll
        for (int h = 0; h < 2; ++h) {
            unsigned y = finv10(p, j0 + h);
            unsigned yh = y >> 5;
            unsigned addr = yh * 32 + ((y & 31u) ^ amul(p, yh));
            e[h] = addr | ((y >> 9) << 15);
        }
        g_T[p][widx] = e[0] | (e[1] << 16);
    }
}

// full-complex gate on k-bit mask M
template<int M>
__device__ __forceinline__ void gate_reg(u64* r, const u64* __restrict__ C) {
    const u64 c00 = C[0], d00 = C[1], c01 = C[2], d01 = C[3];
    const u64 c10 = C[4], d10 = C[5], c11 = C[6], d11 = C[7];
    #pragma unroll
    for (int k = 0; k < 16; ++k) {
        if ((k & M) == 0) {
            const int k1 = k | M;
            u64 a0 = r[k], a1 = r[k1];
            u64 s0 = swp(a0), s1 = swp(a1);
            r[k]  = ffma2(c00, a0, ffma2(d00, s0, ffma2(c01, a1, fmul2(d01, s1))));
            r[k1] = ffma2(c10, a0, ffma2(d10, s0, ffma2(c11, a1, fmul2(d11, s1))));
        }
    }
}

// real RY butterfly on k-bit mask M
template<int M>
__device__ __forceinline__ void ry_reg(u64* r, u64 C, u64 Sp, u64 Sn) {
    #pragma unroll
    for (int k = 0; k < 16; ++k) {
        if ((k & M) == 0) {
            const int k1 = k | M;
            u64 a0 = r[k], a1 = r[k1];
            r[k]  = ffma2(Sn, a1, fmul2(C, a0));
            r[k1] = ffma2(Sp, a0, fmul2(C, a1));
        }
    }
}

// masked per-bit phase fixup: amps with k&M multiplied by ratio (C,D packs)
template<int M>
__device__ __forceinline__ void phase_bit(u64* r, u64 C, u64 D) {
    #pragma unroll
    for (int k = 0; k < 16; ++k) {
        if (k & M)
            r[k] = ffma2(C, r[k], fmul2(D, swp(r[k])));
    }
}

// real RY butterfly on lane-bit xor distance D
template<int D>
__device__ __forceinline__ void ry_shfl(u64* r, u64 cc, u64 ss) {
    #pragma unroll
    for (int k = 0; k < 16; ++k) {
        u64 own = r[k];
        u64 par = __shfl_xor_sync(0xffffffffu, own, D);
        r[k] = ffma2(ss, par, fmul2(cc, own));
    }
}

__global__ __launch_bounds__(TPB, 12) void qsim_kernel(
    const float* __restrict__ x,     // (B, 2*NQ)
    float* __restrict__ out)         // (B, NQ)
{
    __shared__ u64 sc[DIM];                    // 8 KB state scratch
    __shared__ u64 gmat_s[NL * NQ][8];         // 2.5 KB
    __shared__ unsigned Tp_s[2][512];          // 4 KB
    __shared__ float2 venc[NQ][2];
    __shared__ float red[2][NQ];

    const int t    = threadIdx.x;
    const int lane = t & 31;
    const int w    = t >> 5;                   // warp half = qubit-0 bit (j9)
    const int s    = blockIdx.x;
    const float inv_sqrt2 = 0.70710678118654752440f;
    const float pi_f      = 3.14159265358979323846f;

    {
        const u64* src = &g_gmat[0][0];
        u64* dst = &gmat_s[0][0];
        for (int i = t; i < NL * NQ * 8; i += TPB) dst[i] = src[i];
        const unsigned* ts = &g_T[0][0];
        unsigned* td = &Tp_s[0][0];
        for (int i = t; i < 1024; i += TPB) td[i] = ts[i];
    }

    if (t < NQ) {
        int q = t;
        float th = 0.5f * pi_f * (x[s * 2 * NQ + q]      + 1.0f);
        float ph = 0.5f * pi_f * (x[s * 2 * NQ + NQ + q] + 1.0f);
        float st, ct; sincosf(0.5f * th, &st, &ct);
        float sh, ch; sincosf(0.5f * ph, &sh, &ch);
        float a = inv_sqrt2 * (ct - st);
        float b = inv_sqrt2 * (ct + st);
        venc[q][0] = make_float2(a * ch, -a * sh);
        venc[q][1] = make_float2(b * ch,  b * sh);
    }
    __syncthreads();

    // ---- build product state: layout A: j = w*512 + lane*16 + k ----
    u64 r[16];
    {
        float2 L = venc[0][w];
        L = cmulf(L, venc[1][(lane >> 4) & 1]);
        L = cmulf(L, venc[2][(lane >> 3) & 1]);
        L = cmulf(L, venc[3][(lane >> 2) & 1]);
        L = cmulf(L, venc[4][(lane >> 1) & 1]);
        L = cmulf(L, venc[5][lane & 1]);
        float2 RH[4], RL[4];
        #pragma unroll
        for (int h = 0; h < 4; ++h) RH[h] = cmulf(venc[6][(h >> 1) & 1], venc[7][h & 1]);
        #pragma unroll
        for (int l = 0; l < 4; ++l) RL[l] = cmulf(venc[8][(l >> 1) & 1], venc[9][l & 1]);
        #pragma unroll
        for (int k = 0; k < 16; ++k) {
            float2 a = cmulf(L, cmulf(RH[k >> 2], RL[k & 3]));
            r[k] = pack2(a.x, a.y);
        }
    }

    const unsigned l15   = (unsigned)(lane & 15);
    const unsigned lhb   = (unsigned)(lane >> 4);             // lane bit 4
    u64* scw = sc + (w << 9);
    // gather-store hi base: jt>>5 = w<<4 | (lane>>4)<<3 | (k>>1)
    const unsigned baseHi = ((unsigned)w << 4) | (lhb << 3);
    const unsigned bam0 = lhb ? A0_3 : 0u;                     // amul(0, baseHi)
    const unsigned bam1 = (lhb ? A1_3 : 0u) ^ (w ? A1_4 : 0u); // amul(1, baseHi)

    #pragma unroll 1
    for (int layer = 0; layer < NL; ++layer) {
        const u64 (*G)[8] = &gmat_s[layer * NQ];
        const int par = layer & 1;

        // qubits 6..9: full complex gates on k bits (layout A)
        gate_reg<8>(r, G[6]);
        gate_reg<4>(r, G[7]);
        gate_reg<2>(r, G[8]);
        gate_reg<1>(r, G[9]);

        // per-thread pre scalar: exact for qubits 1..5 (all on lane bits here)
        float2 pre = make_float2(1.0f, 0.0f);
        #pragma unroll
        for (int q = 1; q <= 5; ++q) {
            float px, py;
            unpk(G[q][3], px, py);
            if ((lane >> (5 - q)) & 1) py = -py;
            pre = cmulf(pre, make_float2(px, py));
        }
        {
            const u64 Cp = pack2(pre.x, pre.x), Dp = pack2(-pre.y, pre.y);
            #pragma unroll
            for (int k = 0; k < 16; ++k)
                r[k] = ffma2(Cp, r[k], fmul2(Dp, swp(r[k])));
        }

        // qubit 1: real RY via shuffle (lane bit 4)
        ry_shfl<16>(r, G[1][0], (lane & 16) ? G[1][1] : G[1][2]);

        // transpose j[3:0] <-> j[7:4] (within-warp, conflict-free)
        #pragma unroll
        for (int k = 0; k < 16; ++k)
            scw[lane * 16 + (k ^ (int)l15)] = r[k];
        __syncwarp();
        #pragma unroll
        for (int k = 0; k < 16; ++k)
            r[k] = scw[((lane & 16) | k) * 16 + ((int)l15 ^ k)];
        __syncwarp();

        // layout B: k bit b <-> qubit 5-b. RY butterflies for qubits 2..5.
        ry_reg<8>(r, G[2][0], G[2][1], G[2][2]);
        ry_reg<4>(r, G[3][0], G[3][1], G[3][2]);
        ry_reg<2>(r, G[4][0], G[4][1], G[4][2]);
        ry_reg<1>(r, G[5][0], G[5][1], G[5][2]);

        // per-thread post scalar: q1 exact (lane bit 4 unchanged) * POSTBASE(q2..5, bit=0)
        {
            float ox, oy, pbx, pby;
            unpk(G[1][4], ox, oy);
            if (lane & 16) oy = -oy;
            unpk(G[1][5], pbx, pby);
            float2 post = cmulf(make_float2(ox, oy), make_float2(pbx, pby));
            const u64 Cq = pack2(post.x, post.x), Dq = pack2(-post.y, post.y);
            #pragma unroll
            for (int k = 0; k < 16; ++k)
                r[k] = ffma2(Cq, r[k], fmul2(Dq, swp(r[k])));
        }
        // per-bit post ratio fixups for qubits 2..5 (amps with bit=1)
        phase_bit<8>(r, G[2][5], G[2][6]);
        phase_bit<4>(r, G[3][5], G[3][6]);
        phase_bit<2>(r, G[4][5], G[4][6]);
        phase_bit<1>(r, G[5][5], G[5][6]);

        // store at A-swizzled TRUE-index addresses (layout B positions)
        // jt = w<<9 | (lane>>4)<<8 | k<<4 | l15
        const unsigned bam = par ? bam1 : bam0;
        #pragma unroll
        for (int k = 0; k < 16; ++k) {
            const unsigned kk  = (unsigned)k;
            const unsigned hi  = baseHi | (kk >> 1);
            const unsigned lo  = ((kk & 1u) << 4) | l15;
            const unsigned amk = par ? ((kk >> 1) << 1) : (kk >> 1);  // amul(par, k>>1)
            sc[(hi << 5) | (lo ^ bam ^ amk)] = r[k];
        }
        __syncthreads();

        // gather = CNOT ring composed with qubit-0 gate (identical to R9)
        const unsigned PC = par ? PC1 : PC0;
        const u64 q0_0 = G[0][0], q0_1 = G[0][1], q0_2 = G[0][2], q0_3 = G[0][3];
        const u64 q1_0 = G[0][4], q1_1 = G[0][5], q1_2 = G[0][6], q1_3 = G[0][7];
        const unsigned tbase = ((unsigned)w << 8) | ((unsigned)lane << 3);
        #pragma unroll
        for (int c = 0; c < 8; ++c) {
            unsigned tw = Tp_s[par][tbase | ((unsigned)c ^ (unsigned)(lane >> 2))];
            #pragma unroll
            for (int h = 0; h < 2; ++h) {
                unsigned e = (h == 0) ? (tw & 0xffffu) : (tw >> 16);
                unsigned idx = e & 1023u;
                bool bb = (e >> 15) != 0;
                u64 a = sc[idx];
                u64 p = sc[idx ^ PC];
                u64 cA = bb ? q1_0 : q0_0;
                u64 dA = bb ? q1_1 : q0_1;
                u64 cB = bb ? q1_2 : q0_2;
                u64 dB = bb ? q1_3 : q0_3;
                r[2 * c + h] = ffma2(cA, a, ffma2(dA, swp(a), ffma2(cB, p, fmul2(dB, swp(p)))));
            }
        }
        __syncthreads();
    }

    // ---- <Z_q> readout (layout A) ----
    u64 tot = 0, accP[4] = {0,0,0,0}, accN[4] = {0,0,0,0};
    #pragma unroll
    for (int k = 0; k < 16; ++k) {
        u64 sq = fmul2(r[k], r[k]);
        tot = fadd2(tot, sq);
        #pragma unroll
        for (int b = 0; b < 4; ++b) {
            if ((k >> b) & 1) accN[b] = fadd2(accN[b], sq);
            else              accP[b] = fadd2(accP[b], sq);
        }
    }
    float zq[NQ];
    {
        float tl, th; unpk(tot, tl, th);
        float pr_tot = tl + th;
        zq[0] = w ? -pr_tot : pr_tot;
        zq[1] = (lane & 16) ? -pr_tot : pr_tot;
        zq[2] = (lane & 8)  ? -pr_tot : pr_tot;
        zq[3] = (lane & 4)  ? -pr_tot : pr_tot;
        zq[4] = (lane & 2)  ? -pr_tot : pr_tot;
        zq[5] = (lane & 1)  ? -pr_tot : pr_tot;
        #pragma unroll
        for (int b = 0; b < 4; ++b) {
            float pl, ph, nl, nh;
            unpk(accP[b], pl, ph); unpk(accN[b], nl, nh);
            zq[9 - b] = (pl + ph) - (nl + nh);
        }
    }
    #pragma unroll
    for (int q = 0; q < NQ; ++q) {
        #pragma unroll
        for (int o = 16; o > 0; o >>= 1)
            zq[q] += __shfl_xor_sync(0xffffffffu, zq[q], o);
    }
    if (lane == 0) {
        #pragma unroll
        for (int q = 0; q < NQ; ++q) red[w][q] = zq[q];
    }
    __syncthreads();
    if (t < NQ)
        out[s * NQ + t] = red[0][t] + red[1][t];
}

extern "C" void kernel_launch(void* const* d_in, const int* in_sizes, int n_in,
                              void* d_out, int out_size) {
    const float* x = (const float*)d_in[0];
    const float* w = (const float*)d_in[1];
    float* out = (float*)d_out;
    int B = in_sizes[0] / (2 * NQ);   // 4096 flattened samples
    precompute_kernel<<<1, 128>>>(w);
    qsim_kernel<<<B, TPB>>>(x, out);
}